// round 10
// baseline (speedup 1.0000x reference)
#include <cuda_runtime.h>
#include <cstdint>
#include <cstddef>

// AlarmworkRNN reduced form: only state row SEQ-1 (2047) reaches the output,
// so the scan collapses to a 256-step recurrence on two 1024-vectors.
//
// R10 = R9 packets (16B single-copy-atomic {z1, z2, 0, tag}) with the poll
// flood removed and ALL fences/atomics deleted:
//  - only threads 0-127 poll, one sentinel packet (CTA's col-0) each
//  - bulk load of all 1024 packets tag-verifies each packet (micro-spin on
//    stragglers) -- validity travels WITH the data, no ordering needed
//  - producer: lane0 of each warp stores its packet post-compute; no sync,
//    no fence, no atomicExch anywhere in the step loop
// Weights register-resident (R8-proven). Monotonic tags, replay-safe.

#define ND   256
#define SEQ  2048
#define NI   256
#define NH   1024
#define NO   256
#define GRID 128
#define TPB  256
#define H_PER 8
#define O_PER 2
#define PAD  9          // staging transpose pad (conflict-free)
#define CPT  4          // packets bulk-loaded per thread (1024/256)

// Publication k lives in buffer k&1. Packet: {z1_bits, z2_bits, 0, tag}.
__device__ uint4 g_pub[2][NH];    // zero-init; tags monotonic across replays

__device__ __forceinline__ uint4 ldv4(const uint4* p) {
    uint4 v;
    asm volatile("ld.volatile.global.v4.u32 {%0,%1,%2,%3}, [%4];"
                 : "=r"(v.x), "=r"(v.y), "=r"(v.z), "=r"(v.w)
                 : "l"(p) : "memory");
    return v;
}
__device__ __forceinline__ void stv4(uint4* p, uint4 v) {
    asm volatile("st.volatile.global.v4.u32 [%0], {%1,%2,%3,%4};"
                 :: "l"(p), "r"(v.x), "r"(v.y), "r"(v.z), "r"(v.w) : "memory");
}

__device__ __forceinline__ float warp_reduce(float a) {
    #pragma unroll
    for (int off = 16; off; off >>= 1)
        a += __shfl_xor_sync(0xffffffffu, a, off);
    return a;
}

extern __shared__ float smem[];
// floats: stg[9216] z12s[1024] z2s[1024] z1s[1024] xs[256]
#define OFF_STG  0
#define OFF_Z12  9216
#define OFF_Z2   10240
#define OFF_Z1   11264
#define OFF_XS   12288
#define SMEM_FLOATS 12544

__global__ void __launch_bounds__(TPB, 1)
rnn_kernel(const float* __restrict__ x,
           const float* __restrict__ W_in1, const float* __restrict__ b_in1,
           const float* __restrict__ W_rec1,
           const float* __restrict__ W_in2, const float* __restrict__ b_in2,
           const float* __restrict__ W_rec2,
           const float* __restrict__ W_out, const float* __restrict__ b_out,
           float* __restrict__ out) {
    float* stg  = smem + OFF_STG;
    float* z12s = smem + OFF_Z12;
    float* z2s  = smem + OFF_Z2;
    float* z1s  = smem + OFF_Z1;
    float* xs   = smem + OFF_XS;

    const int tid   = threadIdx.x;
    const int cta   = blockIdx.x;
    const int w     = tid >> 5;
    const int lane  = tid & 31;
    const int jbase = cta * H_PER;
    const int kbase = cta * O_PER;
    const int c0    = tid * CPT;          // bulk-load columns

    // Launch-entry tag base: buffer-0 tags are uniform across columns/CTAs.
    const unsigned base = ldv4(&g_pub[0][0]).w;

    // ---- Stage weights into REGISTERS via padded SMEM transpose (R8-verbatim) ----
    float wrec1[32], wrec2[32], win1[8], win2[8], wout[32];

    for (int r = tid >> 3; r < NH; r += 32)                 // W_rec1
        stg[r * PAD + (tid & 7)] = W_rec1[r * NH + jbase + (tid & 7)];
    __syncthreads();
    #pragma unroll
    for (int i = 0; i < 32; i++)
        wrec1[i] = stg[(lane + 32 * i) * PAD + w];
    __syncthreads();

    for (int r = tid >> 3; r < NH; r += 32)                 // W_rec2
        stg[r * PAD + (tid & 7)] = W_rec2[r * NH + jbase + (tid & 7)];
    __syncthreads();
    #pragma unroll
    for (int i = 0; i < 32; i++)
        wrec2[i] = stg[(lane + 32 * i) * PAD + w];
    __syncthreads();

    for (int r = tid >> 3; r < NI; r += 32)                 // W_in1
        stg[r * PAD + (tid & 7)] = W_in1[r * NH + jbase + (tid & 7)];
    __syncthreads();
    #pragma unroll
    for (int i = 0; i < 8; i++)
        win1[i] = stg[(lane + 32 * i) * PAD + w];
    __syncthreads();

    for (int r = tid >> 3; r < NI; r += 32)                 // W_in2
        stg[r * PAD + (tid & 7)] = W_in2[r * NH + jbase + (tid & 7)];
    __syncthreads();
    #pragma unroll
    for (int i = 0; i < 8; i++)
        win2[i] = stg[(lane + 32 * i) * PAD + w];
    __syncthreads();

    for (int r = tid >> 1; r < NH; r += 128)                // W_out (2 cols)
        stg[r * PAD + (tid & 1)] = W_out[r * NO + kbase + (tid & 1)];
    __syncthreads();
    if (w >= 6) {
        #pragma unroll
        for (int i = 0; i < 32; i++)
            wout[i] = stg[(lane + 32 * i) * PAD + (w - 6)];
    }

    const float b1 = b_in1[jbase + w];
    const float b2 = b_in2[jbase + w];
    const float bo = (w >= 6) ? b_out[kbase + (w - 6)] : 0.f;

    float z2reg = 0.f;   // warp-uniform: z2 value of column jbase+w

    // ---- Iteration 0: compute pub 1 from zero state, publish packets ----
    for (int i = tid; i < NH; i += TPB) { z12s[i] = 0.f; z2s[i] = 0.f; }
    xs[tid] = x[(size_t)(SEQ - 1) * NI + tid];          // x row 0
    __syncthreads();
    {
        float a1 = 0.f, a2 = 0.f;
        #pragma unroll
        for (int i = 0; i < 8; i++) {
            const float xv = xs[lane + 32 * i];
            a1 = fmaf(win1[i], xv, a1);
            a2 = fmaf(win2[i], xv, a2);
        }
        #pragma unroll
        for (int i = 0; i < 32; i++) {
            a1 = fmaf(wrec1[i], z12s[lane + 32 * i], a1);
            a2 = fmaf(wrec2[i], z2s [lane + 32 * i], a2);
        }
        a1 = warp_reduce(a1);
        a2 = warp_reduce(a2);
        const float z1n = tanhf(a1 + b1);
        z2reg = tanhf(a2 + b2);
        if (lane == 0) {          // publish pub 1 -> buffer 1, tag base+1
            uint4 pkt;
            pkt.x = __float_as_uint(z1n);
            pkt.y = __float_as_uint(z2reg);
            pkt.z = 0u;
            pkt.w = base + 1u;
            stv4(&g_pub[1][jbase + w], pkt);
        }
    }

    float xpref = __ldg(&x[((size_t)1 * SEQ + (SEQ - 1)) * NI + tid]);  // row 1

    // ---- Iterations 1..ND ----
    for (int t = 1; t <= ND; t++) {
        const int cb   = t & 1;
        const int nbuf = (t + 1) & 1;
        const bool ev  = ((t & 1) == 0);
        const unsigned target = base + (unsigned)t;

        // Phase A: sentinel poll (threads 0-127, one packet each) |
        //          out[t-2] matvec (warps 6-7, reads z1s = pub t-1).
        if (tid < GRID) {
            const uint4* sp = &g_pub[cb][tid * H_PER];
            uint4 s;
            do { s = ldv4(sp); } while ((int)(s.w - target) < 0);
        } else if (w >= 6 && t >= 2) {
            float a = 0.f;
            #pragma unroll
            for (int i = 0; i < 32; i++)
                a = fmaf(wout[i], z1s[lane + 32 * i], a);
            a = warp_reduce(a);
            if (lane == 0)
                out[(size_t)(t - 2) * NO + kbase + (w - 6)] = tanhf(a + bo);
        }
        __syncthreads();

        // Phase B: tag-verified bulk load of own 4 packets (usually 1 round).
        uint4 v0, v1, v2, v3;
        do {
            v0 = ldv4(&g_pub[cb][c0 + 0]);
            v1 = ldv4(&g_pub[cb][c0 + 1]);
            v2 = ldv4(&g_pub[cb][c0 + 2]);
            v3 = ldv4(&g_pub[cb][c0 + 3]);
        } while (((int)(v0.w - target) < 0) | ((int)(v1.w - target) < 0) |
                 ((int)(v2.w - target) < 0) | ((int)(v3.w - target) < 0));
        {
            const float p0 = __uint_as_float(v0.x), q0 = __uint_as_float(v0.y);
            const float p1 = __uint_as_float(v1.x), q1 = __uint_as_float(v1.y);
            const float p2 = __uint_as_float(v2.x), q2 = __uint_as_float(v2.y);
            const float p3 = __uint_as_float(v3.x), q3 = __uint_as_float(v3.y);
            z1s [c0 + 0] = p0; z2s[c0 + 0] = q0; z12s[c0 + 0] = p0 + q0;
            z1s [c0 + 1] = p1; z2s[c0 + 1] = q1; z12s[c0 + 1] = p1 + q1;
            z1s [c0 + 2] = p2; z2s[c0 + 2] = q2; z12s[c0 + 2] = p2 + q2;
            z1s [c0 + 3] = p3; z2s[c0 + 3] = q3; z12s[c0 + 3] = p3 + q3;
        }
        xs[tid] = xpref;
        __syncthreads();

        // Phase C: compute pub t+1, publish packets (no sync/fence needed --
        // packets are self-verifying).
        if (t < ND) {
            float a1 = 0.f, a2 = 0.f;
            #pragma unroll
            for (int i = 0; i < 8; i++) {
                const float xv = xs[lane + 32 * i];
                a1 = fmaf(win1[i], xv, a1);
                if (ev) a2 = fmaf(win2[i], xv, a2);
            }
            #pragma unroll
            for (int i = 0; i < 32; i++) {
                a1 = fmaf(wrec1[i], z12s[lane + 32 * i], a1);
                if (ev) a2 = fmaf(wrec2[i], z2s[lane + 32 * i], a2);
            }
            a1 = warp_reduce(a1);
            if (ev) a2 = warp_reduce(a2);

            const float z1n = tanhf(a1 + b1);
            if (ev) z2reg = tanhf(a2 + b2);
            if (lane == 0) {
                uint4 pkt;
                pkt.x = __float_as_uint(z1n);
                pkt.y = __float_as_uint(z2reg);   // odd t: republish held z2
                pkt.z = 0u;
                pkt.w = target + 1u;
                stv4(&g_pub[nbuf][jbase + w], pkt);
            }
        }

        // Prefetch x row t+1 (consumed next iteration; latency hidden).
        if (t + 1 < ND)
            xpref = __ldg(&x[((size_t)(t + 1) * SEQ + (SEQ - 1)) * NI + tid]);
    }

    // ---- Tail: out[ND-1] from pub ND (z1s staged at t=ND) ----
    if (w >= 6) {
        float a = 0.f;
        #pragma unroll
        for (int i = 0; i < 32; i++)
            a = fmaf(wout[i], z1s[lane + 32 * i], a);
        a = warp_reduce(a);
        if (lane == 0)
            out[(size_t)(ND - 1) * NO + kbase + (w - 6)] = tanhf(a + bo);
    }
}

extern "C" void kernel_launch(void* const* d_in, const int* in_sizes, int n_in,
                              void* d_out, int out_size) {
    const float* x      = (const float*)d_in[0];
    const float* W_in1  = (const float*)d_in[1];
    const float* b_in1  = (const float*)d_in[2];
    const float* W_rec1 = (const float*)d_in[3];
    const float* W_in2  = (const float*)d_in[4];
    const float* b_in2  = (const float*)d_in[5];
    const float* W_rec2 = (const float*)d_in[6];
    const float* W_out  = (const float*)d_in[7];
    const float* b_out  = (const float*)d_in[8];
    float* out = (float*)d_out;

    const size_t shmem = SMEM_FLOATS * sizeof(float);
    cudaFuncSetAttribute(rnn_kernel, cudaFuncAttributeMaxDynamicSharedMemorySize,
                         (int)shmem);
    rnn_kernel<<<GRID, TPB, shmem>>>(x, W_in1, b_in1, W_rec1,
                                     W_in2, b_in2, W_rec2, W_out, b_out, out);
}